// round 9
// baseline (speedup 1.0000x reference)
#include <cuda_runtime.h>
#include <cuda_fp16.h>
#include <cuda_bf16.h>
#include <cstdint>

#define NN 50000
#define NE 800000
#define NP 200000
#define FD 128
#define KSTEPS 10
#define SCAN_BS 512
#define SCAN_NB ((NN + SCAN_BS - 1) / SCAN_BS)   // 98

// ---- scratch (device globals; no allocation allowed) ----
__device__ int      g_cnt[NN];
__device__ int      g_rowptr[NN + 1];
__device__ int      g_cursor[NN];
__device__ int      g_aux[SCAN_NB];
__device__ float    g_dinv[NN];
__device__ float    g_self[NN];             // 0.9 * dinv^2 (self-loop coef)
__device__ uint32_t g_csr[NE];              // low16 = src, high16 = fp16(0.9*dinv[s]*dinv[d])
__device__ __half   g_a0[(size_t)NN * FD];  // fp16 teleport anchor = 0.1 * h0
__device__ __half   g_ha16[(size_t)NN * FD];
__device__ __half   g_hb16[(size_t)NN * FD];
__device__ __half   g_W1h[FD * FD];
__device__ __half   g_W2h[FD * FD];

static __device__ __forceinline__ uint32_t smem_u32(const void* p) {
    uint32_t a;
    asm("{ .reg .u64 t; cvta.to.shared.u64 t, %1; cvt.u32.u64 %0, t; }" : "=r"(a) : "l"(p));
    return a;
}

// ---------------- fused: weight fp32->fp16 + zero cnt ----------------
__global__ void k_prep(const float* __restrict__ W1, const float* __restrict__ W2,
                       __half* __restrict__ W1h, __half* __restrict__ W2h,
                       int* __restrict__ cnt) {
    int i = blockIdx.x * blockDim.x + threadIdx.x;
    if (i < NN) cnt[i] = 0;
    if (i < 4096) {
        float4 w = __ldg((const float4*)W1 + i);
        __half2 p0 = __floats2half2_rn(w.x, w.y);
        __half2 p1 = __floats2half2_rn(w.z, w.w);
        ((uint2*)W1h)[i] = make_uint2(*(unsigned*)&p0, *(unsigned*)&p1);
    } else if (i < 8192) {
        int j = i - 4096;
        float4 w = __ldg((const float4*)W2 + j);
        __half2 p0 = __floats2half2_rn(w.x, w.y);
        __half2 p1 = __floats2half2_rn(w.z, w.w);
        ((uint2*)W2h)[j] = make_uint2(*(unsigned*)&p0, *(unsigned*)&p1);
    }
}

__global__ void k_count(const int* __restrict__ dst, int* __restrict__ cnt) {
    int e = blockIdx.x * blockDim.x + threadIdx.x;
    if (e < NE) atomicAdd(&cnt[dst[e]], 1);
}

// scan_block fused with dinv/selfc computation (both read cnt)
__global__ void __launch_bounds__(SCAN_BS) k_scan_block(const int* __restrict__ cnt,
                                                        int* __restrict__ rowptr,
                                                        int* __restrict__ aux,
                                                        float* __restrict__ dinv,
                                                        float* __restrict__ selfc) {
    __shared__ int s[SCAN_BS];
    int i = blockIdx.x * SCAN_BS + threadIdx.x;
    int v = (i < NN) ? cnt[i] : 0;
    if (i < NN) {
        float d = rsqrtf((float)(v + 1));  // +1 self loop
        dinv[i] = d;
        selfc[i] = 0.9f * d * d;
    }
    s[threadIdx.x] = v;
    __syncthreads();
#pragma unroll
    for (int off = 1; off < SCAN_BS; off <<= 1) {
        int t = (threadIdx.x >= off) ? s[threadIdx.x - off] : 0;
        __syncthreads();
        s[threadIdx.x] += t;
        __syncthreads();
    }
    if (i < NN) rowptr[i] = s[threadIdx.x] - v;  // exclusive
    if (threadIdx.x == SCAN_BS - 1) aux[blockIdx.x] = s[threadIdx.x];
}

__global__ void __launch_bounds__(128) k_scan_aux(int* __restrict__ aux) {
    __shared__ int s[128];
    int v = (threadIdx.x < SCAN_NB) ? aux[threadIdx.x] : 0;
    s[threadIdx.x] = v;
    __syncthreads();
#pragma unroll
    for (int off = 1; off < 128; off <<= 1) {
        int t = (threadIdx.x >= off) ? s[threadIdx.x - off] : 0;
        __syncthreads();
        s[threadIdx.x] += t;
        __syncthreads();
    }
    if (threadIdx.x < SCAN_NB) aux[threadIdx.x] = s[threadIdx.x] - v;  // exclusive
}

__global__ void k_scan_add(int* __restrict__ rowptr, const int* __restrict__ aux,
                           int* __restrict__ cursor) {
    int i = blockIdx.x * blockDim.x + threadIdx.x;
    if (i < NN) {
        int r = rowptr[i] + aux[i / SCAN_BS];
        rowptr[i] = r;
        cursor[i] = r;
    }
    if (i == 0) rowptr[NN] = NE;
}

__global__ void k_fill(const int* __restrict__ src, const int* __restrict__ dst,
                       const float* __restrict__ dinv, int* __restrict__ cursor,
                       uint32_t* __restrict__ csr) {
    int e = blockIdx.x * blockDim.x + threadIdx.x;
    if (e >= NE) return;
    int s = src[e], d = dst[e];
    int pos = atomicAdd(&cursor[d], 1);
    __half w = __float2half(0.9f * dinv[s] * dinv[d]);
    csr[pos] = (uint32_t)s | ((uint32_t)__half_as_ushort(w) << 16);
}

// ---------------- tensor-core GEMM: out = act(A)[rows,128] @ Wh[128,128]^T + b ----------------
template <bool RELU, bool IN_HALF>
__global__ void __launch_bounds__(128) k_gemm_tc(const void* __restrict__ Ain,
                                                 const __half* __restrict__ Wh,
                                                 const float* __restrict__ bias,
                                                 __half* __restrict__ anchor,
                                                 __half* __restrict__ out16, int rows) {
    __shared__ __half Ws[128][136];
    __shared__ __half As[32][136];

    int tid = threadIdx.x;
    int lane = tid & 31, warp = tid >> 5;
    int rowbase = blockIdx.x * 32;

    for (int t = tid; t < 2048; t += 128) {
        int j = t >> 4, g = t & 15;
        uint4 w = __ldg((const uint4*)(Wh + j * 128) + g);
        *(uint4*)&Ws[j][g * 8] = w;
    }
    for (int t = tid; t < 1024; t += 128) {
        int r = t >> 5, kq = t & 31;
        int row = rowbase + r;
        float4 v = make_float4(0.f, 0.f, 0.f, 0.f);
        if (row < rows) {
            if (IN_HALF) {
                uint2 u = __ldg((const uint2*)((const __half*)Ain + (size_t)row * 128 + kq * 4));
                float2 f01 = __half22float2(*(__half2*)&u.x);
                float2 f23 = __half22float2(*(__half2*)&u.y);
                v = make_float4(f01.x, f01.y, f23.x, f23.y);
            } else {
                v = __ldg((const float4*)((const float*)Ain + (size_t)row * 128 + kq * 4));
            }
        }
        if (RELU) {
            v.x = fmaxf(v.x, 0.f); v.y = fmaxf(v.y, 0.f);
            v.z = fmaxf(v.z, 0.f); v.w = fmaxf(v.w, 0.f);
        }
        __half2 p0 = __floats2half2_rn(v.x, v.y);
        __half2 p1 = __floats2half2_rn(v.z, v.w);
        *(uint2*)&As[r][kq * 4] = make_uint2(*(unsigned*)&p0, *(unsigned*)&p1);
    }
    __syncthreads();

    int r0 = (warp >> 1) * 16;
    int jbase = (warp & 1) * 64;

    uint32_t as_base = smem_u32(&As[0][0]);
    uint32_t ws_base = smem_u32(&Ws[0][0]);
    uint32_t a_addr0 = as_base + (uint32_t)(((r0 + (lane & 15)) * 136 + ((lane >> 4) * 8)) * 2);
    uint32_t b_addr0 = ws_base + (uint32_t)((((jbase + (lane & 7)) * 136) + (((lane >> 3) & 1) * 8)) * 2);

    float d[8][4];
#pragma unroll
    for (int t = 0; t < 8; t++)
        d[t][0] = d[t][1] = d[t][2] = d[t][3] = 0.f;

#pragma unroll
    for (int k0 = 0; k0 < 128; k0 += 16) {
        uint32_t a0, a1, a2, a3;
        asm volatile("ldmatrix.sync.aligned.m8n8.x4.shared.b16 {%0,%1,%2,%3}, [%4];"
                     : "=r"(a0), "=r"(a1), "=r"(a2), "=r"(a3)
                     : "r"(a_addr0 + (uint32_t)(k0 * 2)));
#pragma unroll
        for (int t = 0; t < 8; t++) {
            uint32_t b0, b1;
            asm volatile("ldmatrix.sync.aligned.m8n8.x2.shared.b16 {%0,%1}, [%2];"
                         : "=r"(b0), "=r"(b1)
                         : "r"(b_addr0 + (uint32_t)((t * 8 * 136 + k0) * 2)));
            asm volatile("mma.sync.aligned.m16n8k16.row.col.f32.f16.f16.f32 "
                         "{%0,%1,%2,%3}, {%4,%5,%6,%7}, {%8,%9}, {%0,%1,%2,%3};"
                         : "+f"(d[t][0]), "+f"(d[t][1]), "+f"(d[t][2]), "+f"(d[t][3])
                         : "r"(a0), "r"(a1), "r"(a2), "r"(a3), "r"(b0), "r"(b1));
        }
    }

    int row0 = rowbase + r0 + (lane >> 2);
    int row1 = row0 + 8;
#pragma unroll
    for (int t = 0; t < 8; t++) {
        int col = jbase + t * 8 + 2 * (lane & 3);
        float bx = __ldg(&bias[col]);
        float by = __ldg(&bias[col + 1]);
        if (row0 < rows) {
            float v0 = d[t][0] + bx, v1 = d[t][1] + by;
            __half2 hs = __floats2half2_rn(v0, v1);
            __half2 hanc = __floats2half2_rn(0.1f * v0, 0.1f * v1);
            *(unsigned*)(out16 + (size_t)row0 * 128 + col) = *(unsigned*)&hs;
            *(unsigned*)(anchor + (size_t)row0 * 128 + col) = *(unsigned*)&hanc;
        }
        if (row1 < rows) {
            float v2 = d[t][2] + bx, v3 = d[t][3] + by;
            __half2 hs = __floats2half2_rn(v2, v3);
            __half2 hanc = __floats2half2_rn(0.1f * v2, 0.1f * v3);
            *(unsigned*)(out16 + (size_t)row1 * 128 + col) = *(unsigned*)&hs;
            *(unsigned*)(anchor + (size_t)row1 * 128 + col) = *(unsigned*)&hanc;
        }
    }
}

// ---------------- fused APPNP step (fp16 state + anchor, packed 4B edges, 4x MLP) ----------------
// out[v] = a0[v] + selfc[v]*h[v] + sum_{e: dst=v} w[e]*h[src[e]]
__global__ void __launch_bounds__(256) k_prop16(const int* __restrict__ rowptr,
                                                const uint32_t* __restrict__ csr,
                                                const __half* __restrict__ h,
                                                const __half* __restrict__ a0,
                                                const float* __restrict__ selfc,
                                                __half* __restrict__ out) {
    int v = (blockIdx.x * blockDim.x + threadIdx.x) >> 5;
    int lane = threadIdx.x & 31;
    if (v >= NN) return;

    float sc = __ldg(&selfc[v]);
    uint2 hr = ((const uint2*)(h + (size_t)v * FD))[lane];
    float2 h01 = __half22float2(*(__half2*)&hr.x);
    float2 h23 = __half22float2(*(__half2*)&hr.y);
    uint2 ar = ((const uint2*)(a0 + (size_t)v * FD))[lane];
    float2 a01 = __half22float2(*(__half2*)&ar.x);
    float2 a23 = __half22float2(*(__half2*)&ar.y);
    float ax = fmaf(sc, h01.x, a01.x);
    float ay = fmaf(sc, h01.y, a01.y);
    float az = fmaf(sc, h23.x, a23.x);
    float aw = fmaf(sc, h23.y, a23.y);

    int beg = __ldg(&rowptr[v]);
    int end = __ldg(&rowptr[v + 1]);

    for (int j0 = beg; j0 < end; j0 += 32) {
        uint32_t ent = (j0 + lane < end) ? __ldg(&csr[j0 + lane]) : 0u;
        int kmax = min(32, end - j0);
        int k = 0;
        // 4-wide: four independent shfl->LDG chains in flight
        for (; k + 4 <= kmax; k += 4) {
            uint32_t e0 = __shfl_sync(0xFFFFFFFFu, ent, k);
            uint32_t e1 = __shfl_sync(0xFFFFFFFFu, ent, k + 1);
            uint32_t e2 = __shfl_sync(0xFFFFFFFFu, ent, k + 2);
            uint32_t e3 = __shfl_sync(0xFFFFFFFFu, ent, k + 3);
            uint2 r0 = __ldg((const uint2*)(h + (size_t)(e0 & 0xFFFFu) * FD) + lane);
            uint2 r1 = __ldg((const uint2*)(h + (size_t)(e1 & 0xFFFFu) * FD) + lane);
            uint2 r2 = __ldg((const uint2*)(h + (size_t)(e2 & 0xFFFFu) * FD) + lane);
            uint2 r3 = __ldg((const uint2*)(h + (size_t)(e3 & 0xFFFFu) * FD) + lane);
            float c0 = __half2float(__ushort_as_half((unsigned short)(e0 >> 16)));
            float c1 = __half2float(__ushort_as_half((unsigned short)(e1 >> 16)));
            float c2 = __half2float(__ushort_as_half((unsigned short)(e2 >> 16)));
            float c3 = __half2float(__ushort_as_half((unsigned short)(e3 >> 16)));
            float2 s01, s23;
            s01 = __half22float2(*(__half2*)&r0.x); s23 = __half22float2(*(__half2*)&r0.y);
            ax = fmaf(c0, s01.x, ax); ay = fmaf(c0, s01.y, ay);
            az = fmaf(c0, s23.x, az); aw = fmaf(c0, s23.y, aw);
            s01 = __half22float2(*(__half2*)&r1.x); s23 = __half22float2(*(__half2*)&r1.y);
            ax = fmaf(c1, s01.x, ax); ay = fmaf(c1, s01.y, ay);
            az = fmaf(c1, s23.x, az); aw = fmaf(c1, s23.y, aw);
            s01 = __half22float2(*(__half2*)&r2.x); s23 = __half22float2(*(__half2*)&r2.y);
            ax = fmaf(c2, s01.x, ax); ay = fmaf(c2, s01.y, ay);
            az = fmaf(c2, s23.x, az); aw = fmaf(c2, s23.y, aw);
            s01 = __half22float2(*(__half2*)&r3.x); s23 = __half22float2(*(__half2*)&r3.y);
            ax = fmaf(c3, s01.x, ax); ay = fmaf(c3, s01.y, ay);
            az = fmaf(c3, s23.x, az); aw = fmaf(c3, s23.y, aw);
        }
        for (; k < kmax; k++) {
            uint32_t e = __shfl_sync(0xFFFFFFFFu, ent, k);
            uint2 sr = __ldg((const uint2*)(h + (size_t)(e & 0xFFFFu) * FD) + lane);
            float c = __half2float(__ushort_as_half((unsigned short)(e >> 16)));
            float2 s01 = __half22float2(*(__half2*)&sr.x);
            float2 s23 = __half22float2(*(__half2*)&sr.y);
            ax = fmaf(c, s01.x, ax);
            ay = fmaf(c, s01.y, ay);
            az = fmaf(c, s23.x, az);
            aw = fmaf(c, s23.y, aw);
        }
    }
    __half2 o01 = __floats2half2_rn(ax, ay);
    __half2 o23 = __floats2half2_rn(az, aw);
    ((uint2*)(out + (size_t)v * FD))[lane] = make_uint2(*(unsigned*)&o01, *(unsigned*)&o23);
}

// ---------------- pair head (fp16 features) ----------------
__global__ void __launch_bounds__(256) k_pairs(const __half* __restrict__ h,
                                               const int* __restrict__ idx,
                                               const float* __restrict__ W3,
                                               const float* __restrict__ b3,
                                               float* __restrict__ out) {
    __shared__ float w[512];
    for (int t = threadIdx.x; t < 512; t += 256) w[t] = W3[t];
    __syncthreads();

    int p = (blockIdx.x * blockDim.x + threadIdx.x) >> 5;
    int lane = threadIdx.x & 31;
    if (p >= NP) return;

    int i0 = __ldg(&idx[2 * p]);
    int i1 = __ldg(&idx[2 * p + 1]);
    uint2 ar = ((const uint2*)(h + (size_t)i0 * FD))[lane];
    uint2 br = ((const uint2*)(h + (size_t)i1 * FD))[lane];
    float2 a01 = __half22float2(*(__half2*)&ar.x);
    float2 a23 = __half22float2(*(__half2*)&ar.y);
    float2 b01 = __half22float2(*(__half2*)&br.x);
    float2 b23 = __half22float2(*(__half2*)&br.y);
    float4 a = make_float4(fmaxf(a01.x, 0.f), fmaxf(a01.y, 0.f), fmaxf(a23.x, 0.f), fmaxf(a23.y, 0.f));
    float4 b = make_float4(fmaxf(b01.x, 0.f), fmaxf(b01.y, 0.f), fmaxf(b23.x, 0.f), fmaxf(b23.y, 0.f));

    float4 wa0 = *(const float4*)&w[lane * 4];
    float4 wb0 = *(const float4*)&w[128 + lane * 4];
    float4 wa1 = *(const float4*)&w[256 + lane * 4];
    float4 wb1 = *(const float4*)&w[384 + lane * 4];

    float s0 = a.x * wa0.x + a.y * wa0.y + a.z * wa0.z + a.w * wa0.w
             + b.x * wb0.x + b.y * wb0.y + b.z * wb0.z + b.w * wb0.w;
    float s1 = a.x * wa1.x + a.y * wa1.y + a.z * wa1.z + a.w * wa1.w
             + b.x * wb1.x + b.y * wb1.y + b.z * wb1.z + b.w * wb1.w;

#pragma unroll
    for (int o = 16; o > 0; o >>= 1) {
        s0 += __shfl_xor_sync(0xFFFFFFFFu, s0, o);
        s1 += __shfl_xor_sync(0xFFFFFFFFu, s1, o);
    }
    if (lane == 0) {
        float o0 = s0 + __ldg(&b3[0]);
        float o1 = s1 + __ldg(&b3[1]);
        float m = fmaxf(o0, o1);
        float lse = m + logf(expf(o0 - m) + expf(o1 - m));
        out[2 * p] = o0 - lse;
        out[2 * p + 1] = o1 - lse;
    }
}

// ---------------- launcher ----------------
extern "C" void kernel_launch(void* const* d_in, const int* in_sizes, int n_in,
                              void* d_out, int out_size) {
    const float* x     = (const float*)d_in[0];
    const int*   ei    = (const int*)d_in[1];
    const int*   index = (const int*)d_in[2];
    const float* W1    = (const float*)d_in[3];
    const float* b1    = (const float*)d_in[4];
    const float* W2    = (const float*)d_in[5];
    const float* b2    = (const float*)d_in[6];
    const float* W3    = (const float*)d_in[7];
    const float* b3    = (const float*)d_in[8];
    float* out = (float*)d_out;

    const int* src = ei;       // edge_index[0]
    const int* dst = ei + NE;  // edge_index[1]

    int *cnt, *rowptr, *cursor, *aux;
    float *dinv, *selfc;
    __half *a0, *ha16, *hb16, *W1h, *W2h;
    uint32_t* csr;
    cudaGetSymbolAddress((void**)&cnt, g_cnt);
    cudaGetSymbolAddress((void**)&rowptr, g_rowptr);
    cudaGetSymbolAddress((void**)&cursor, g_cursor);
    cudaGetSymbolAddress((void**)&aux, g_aux);
    cudaGetSymbolAddress((void**)&dinv, g_dinv);
    cudaGetSymbolAddress((void**)&selfc, g_self);
    cudaGetSymbolAddress((void**)&csr, g_csr);
    cudaGetSymbolAddress((void**)&a0, g_a0);
    cudaGetSymbolAddress((void**)&ha16, g_ha16);
    cudaGetSymbolAddress((void**)&hb16, g_hb16);
    cudaGetSymbolAddress((void**)&W1h, g_W1h);
    cudaGetSymbolAddress((void**)&W2h, g_W2h);

    const int nodeG = (NN + 255) / 256;
    const int edgeG = (NE + 255) / 256;

    // prep + CSR build (once per launch)
    k_prep<<<nodeG, 256>>>(W1, W2, W1h, W2h, cnt);
    k_count<<<edgeG, 256>>>(dst, cnt);
    k_scan_block<<<SCAN_NB, SCAN_BS>>>(cnt, rowptr, aux, dinv, selfc);
    k_scan_aux<<<1, 128>>>(aux);
    k_scan_add<<<nodeG, 256>>>(rowptr, aux, cursor);
    k_fill<<<edgeG, 256>>>(src, dst, dinv, cursor, csr);

    const int gemm_grid = (NN + 31) / 32;
    const int warpNodeG = (int)(((size_t)NN * 32 + 255) / 256);
    const int pair_grid = (int)(((size_t)NP * 32 + 255) / 256);

    // h0 = x @ W1^T + b1  (fp16 anchor 0.1*h0 + fp16 state), tensor cores
    k_gemm_tc<false, false><<<gemm_grid, 128>>>(x, W1h, b1, a0, ha16, NN);

    // APPNP #1
    __half* bufs[2] = {hb16, ha16};
    __half* cur = ha16;
    for (int it = 0; it < KSTEPS; it++) {
        __half* nxt = bufs[it & 1];
        k_prop16<<<warpNodeG, 256>>>(rowptr, csr, cur, a0, selfc, nxt);
        cur = nxt;
    }

    // GEMM2: anchor/state from relu(cur) @ W2^T + b2 (state into ha16)
    k_gemm_tc<true, true><<<gemm_grid, 128>>>(cur, W2h, b2, a0, ha16, NN);

    // APPNP #2
    cur = ha16;
    for (int it = 0; it < KSTEPS; it++) {
        __half* nxt = bufs[it & 1];
        k_prop16<<<warpNodeG, 256>>>(rowptr, csr, cur, a0, selfc, nxt);
        cur = nxt;
    }

    // pair head on relu(cur)
    k_pairs<<<pair_grid, 256>>>(cur, index, W3, b3, out);
}

// round 10
// speedup vs baseline: 1.5184x; 1.5184x over previous
#include <cuda_runtime.h>
#include <cuda_fp16.h>
#include <cuda_bf16.h>
#include <cstdint>

#define NN 50000
#define NE 800000
#define NP 200000
#define FD 128
#define KSTEPS 10
#define SCAN_BS 512
#define SCAN_NB ((NN + SCAN_BS - 1) / SCAN_BS)   // 98

// ---- scratch (device globals; no allocation allowed) ----
__device__ int    g_cnt[NN];
__device__ int    g_rowptr[NN + 1];
__device__ int    g_cursor[NN];
__device__ int    g_aux[SCAN_NB];
__device__ float  g_dinv[NN];
__device__ float  g_self[NN];             // 0.9 * dinv^2 (self-loop coef)
__device__ int2   g_csr[NE];              // .x = src, .y = bitcast(0.9*dinv[s]*dinv[d])
__device__ __half g_a0[(size_t)NN * FD];  // fp16 teleport anchor = 0.1 * h0
__device__ __half g_ha16[(size_t)NN * FD];
__device__ __half g_hb16[(size_t)NN * FD];
__device__ __half g_W1h[FD * FD];
__device__ __half g_W2h[FD * FD];

static __device__ __forceinline__ uint32_t smem_u32(const void* p) {
    uint32_t a;
    asm("{ .reg .u64 t; cvta.to.shared.u64 t, %1; cvt.u32.u64 %0, t; }" : "=r"(a) : "l"(p));
    return a;
}

// ---------------- fused: weight fp32->fp16 + zero cnt ----------------
__global__ void k_prep(const float* __restrict__ W1, const float* __restrict__ W2,
                       __half* __restrict__ W1h, __half* __restrict__ W2h,
                       int* __restrict__ cnt) {
    int i = blockIdx.x * blockDim.x + threadIdx.x;
    if (i < NN) cnt[i] = 0;
    if (i < 4096) {
        float4 w = __ldg((const float4*)W1 + i);
        __half2 p0 = __floats2half2_rn(w.x, w.y);
        __half2 p1 = __floats2half2_rn(w.z, w.w);
        ((uint2*)W1h)[i] = make_uint2(*(unsigned*)&p0, *(unsigned*)&p1);
    } else if (i < 8192) {
        int j = i - 4096;
        float4 w = __ldg((const float4*)W2 + j);
        __half2 p0 = __floats2half2_rn(w.x, w.y);
        __half2 p1 = __floats2half2_rn(w.z, w.w);
        ((uint2*)W2h)[j] = make_uint2(*(unsigned*)&p0, *(unsigned*)&p1);
    }
}

__global__ void k_count(const int* __restrict__ dst, int* __restrict__ cnt) {
    int e = blockIdx.x * blockDim.x + threadIdx.x;
    if (e < NE) atomicAdd(&cnt[dst[e]], 1);
}

// scan_block fused with dinv/selfc computation (both read cnt)
__global__ void __launch_bounds__(SCAN_BS) k_scan_block(const int* __restrict__ cnt,
                                                        int* __restrict__ rowptr,
                                                        int* __restrict__ aux,
                                                        float* __restrict__ dinv,
                                                        float* __restrict__ selfc) {
    __shared__ int s[SCAN_BS];
    int i = blockIdx.x * SCAN_BS + threadIdx.x;
    int v = (i < NN) ? cnt[i] : 0;
    if (i < NN) {
        float d = rsqrtf((float)(v + 1));  // +1 self loop
        dinv[i] = d;
        selfc[i] = 0.9f * d * d;
    }
    s[threadIdx.x] = v;
    __syncthreads();
#pragma unroll
    for (int off = 1; off < SCAN_BS; off <<= 1) {
        int t = (threadIdx.x >= off) ? s[threadIdx.x - off] : 0;
        __syncthreads();
        s[threadIdx.x] += t;
        __syncthreads();
    }
    if (i < NN) rowptr[i] = s[threadIdx.x] - v;  // exclusive
    if (threadIdx.x == SCAN_BS - 1) aux[blockIdx.x] = s[threadIdx.x];
}

__global__ void __launch_bounds__(128) k_scan_aux(int* __restrict__ aux) {
    __shared__ int s[128];
    int v = (threadIdx.x < SCAN_NB) ? aux[threadIdx.x] : 0;
    s[threadIdx.x] = v;
    __syncthreads();
#pragma unroll
    for (int off = 1; off < 128; off <<= 1) {
        int t = (threadIdx.x >= off) ? s[threadIdx.x - off] : 0;
        __syncthreads();
        s[threadIdx.x] += t;
        __syncthreads();
    }
    if (threadIdx.x < SCAN_NB) aux[threadIdx.x] = s[threadIdx.x] - v;  // exclusive
}

__global__ void k_scan_add(int* __restrict__ rowptr, const int* __restrict__ aux,
                           int* __restrict__ cursor) {
    int i = blockIdx.x * blockDim.x + threadIdx.x;
    if (i < NN) {
        int r = rowptr[i] + aux[i / SCAN_BS];
        rowptr[i] = r;
        cursor[i] = r;
    }
    if (i == 0) rowptr[NN] = NE;
}

__global__ void k_fill(const int* __restrict__ src, const int* __restrict__ dst,
                       const float* __restrict__ dinv, int* __restrict__ cursor,
                       int2* __restrict__ csr) {
    int e = blockIdx.x * blockDim.x + threadIdx.x;
    if (e >= NE) return;
    int s = src[e], d = dst[e];
    int pos = atomicAdd(&cursor[d], 1);
    float w = 0.9f * dinv[s] * dinv[d];
    csr[pos] = make_int2(s, __float_as_int(w));
}

// ---------------- tensor-core GEMM: out = act(A)[rows,128] @ Wh[128,128]^T + b ----------------
template <bool RELU, bool IN_HALF>
__global__ void __launch_bounds__(128) k_gemm_tc(const void* __restrict__ Ain,
                                                 const __half* __restrict__ Wh,
                                                 const float* __restrict__ bias,
                                                 __half* __restrict__ anchor,
                                                 __half* __restrict__ out16, int rows) {
    __shared__ __half Ws[128][136];
    __shared__ __half As[32][136];

    int tid = threadIdx.x;
    int lane = tid & 31, warp = tid >> 5;
    int rowbase = blockIdx.x * 32;

    for (int t = tid; t < 2048; t += 128) {
        int j = t >> 4, g = t & 15;
        uint4 w = __ldg((const uint4*)(Wh + j * 128) + g);
        *(uint4*)&Ws[j][g * 8] = w;
    }
    for (int t = tid; t < 1024; t += 128) {
        int r = t >> 5, kq = t & 31;
        int row = rowbase + r;
        float4 v = make_float4(0.f, 0.f, 0.f, 0.f);
        if (row < rows) {
            if (IN_HALF) {
                uint2 u = __ldg((const uint2*)((const __half*)Ain + (size_t)row * 128 + kq * 4));
                float2 f01 = __half22float2(*(__half2*)&u.x);
                float2 f23 = __half22float2(*(__half2*)&u.y);
                v = make_float4(f01.x, f01.y, f23.x, f23.y);
            } else {
                v = __ldg((const float4*)((const float*)Ain + (size_t)row * 128 + kq * 4));
            }
        }
        if (RELU) {
            v.x = fmaxf(v.x, 0.f); v.y = fmaxf(v.y, 0.f);
            v.z = fmaxf(v.z, 0.f); v.w = fmaxf(v.w, 0.f);
        }
        __half2 p0 = __floats2half2_rn(v.x, v.y);
        __half2 p1 = __floats2half2_rn(v.z, v.w);
        *(uint2*)&As[r][kq * 4] = make_uint2(*(unsigned*)&p0, *(unsigned*)&p1);
    }
    __syncthreads();

    int r0 = (warp >> 1) * 16;
    int jbase = (warp & 1) * 64;

    uint32_t as_base = smem_u32(&As[0][0]);
    uint32_t ws_base = smem_u32(&Ws[0][0]);
    uint32_t a_addr0 = as_base + (uint32_t)(((r0 + (lane & 15)) * 136 + ((lane >> 4) * 8)) * 2);
    uint32_t b_addr0 = ws_base + (uint32_t)((((jbase + (lane & 7)) * 136) + (((lane >> 3) & 1) * 8)) * 2);

    float d[8][4];
#pragma unroll
    for (int t = 0; t < 8; t++)
        d[t][0] = d[t][1] = d[t][2] = d[t][3] = 0.f;

#pragma unroll
    for (int k0 = 0; k0 < 128; k0 += 16) {
        uint32_t a0, a1, a2, a3;
        asm volatile("ldmatrix.sync.aligned.m8n8.x4.shared.b16 {%0,%1,%2,%3}, [%4];"
                     : "=r"(a0), "=r"(a1), "=r"(a2), "=r"(a3)
                     : "r"(a_addr0 + (uint32_t)(k0 * 2)));
#pragma unroll
        for (int t = 0; t < 8; t++) {
            uint32_t b0, b1;
            asm volatile("ldmatrix.sync.aligned.m8n8.x2.shared.b16 {%0,%1}, [%2];"
                         : "=r"(b0), "=r"(b1)
                         : "r"(b_addr0 + (uint32_t)((t * 8 * 136 + k0) * 2)));
            asm volatile("mma.sync.aligned.m16n8k16.row.col.f32.f16.f16.f32 "
                         "{%0,%1,%2,%3}, {%4,%5,%6,%7}, {%8,%9}, {%0,%1,%2,%3};"
                         : "+f"(d[t][0]), "+f"(d[t][1]), "+f"(d[t][2]), "+f"(d[t][3])
                         : "r"(a0), "r"(a1), "r"(a2), "r"(a3), "r"(b0), "r"(b1));
        }
    }

    int row0 = rowbase + r0 + (lane >> 2);
    int row1 = row0 + 8;
#pragma unroll
    for (int t = 0; t < 8; t++) {
        int col = jbase + t * 8 + 2 * (lane & 3);
        float bx = __ldg(&bias[col]);
        float by = __ldg(&bias[col + 1]);
        if (row0 < rows) {
            float v0 = d[t][0] + bx, v1 = d[t][1] + by;
            __half2 hs = __floats2half2_rn(v0, v1);
            __half2 hanc = __floats2half2_rn(0.1f * v0, 0.1f * v1);
            *(unsigned*)(out16 + (size_t)row0 * 128 + col) = *(unsigned*)&hs;
            *(unsigned*)(anchor + (size_t)row0 * 128 + col) = *(unsigned*)&hanc;
        }
        if (row1 < rows) {
            float v2 = d[t][2] + bx, v3 = d[t][3] + by;
            __half2 hs = __floats2half2_rn(v2, v3);
            __half2 hanc = __floats2half2_rn(0.1f * v2, 0.1f * v3);
            *(unsigned*)(out16 + (size_t)row1 * 128 + col) = *(unsigned*)&hs;
            *(unsigned*)(anchor + (size_t)row1 * 128 + col) = *(unsigned*)&hanc;
        }
    }
}

// ---------------- fused APPNP step (fp16 state + fp16 anchor, fp32 accumulation) ----------------
// EXACT R8 form (known-good 564us): int2 CSR, single gather chain per k.
// out[v] = a0[v] + selfc[v]*h[v] + sum_{e: dst=v} w[e]*h[src[e]]
__global__ void __launch_bounds__(256) k_prop16(const int* __restrict__ rowptr,
                                                const int2* __restrict__ csr,
                                                const __half* __restrict__ h,
                                                const __half* __restrict__ a0,
                                                const float* __restrict__ selfc,
                                                __half* __restrict__ out) {
    int v = (blockIdx.x * blockDim.x + threadIdx.x) >> 5;
    int lane = threadIdx.x & 31;
    if (v >= NN) return;

    float sc = __ldg(&selfc[v]);
    uint2 hr = ((const uint2*)(h + (size_t)v * FD))[lane];
    float2 h01 = __half22float2(*(__half2*)&hr.x);
    float2 h23 = __half22float2(*(__half2*)&hr.y);
    uint2 ar = ((const uint2*)(a0 + (size_t)v * FD))[lane];
    float2 a01 = __half22float2(*(__half2*)&ar.x);
    float2 a23 = __half22float2(*(__half2*)&ar.y);
    float ax = fmaf(sc, h01.x, a01.x);
    float ay = fmaf(sc, h01.y, a01.y);
    float az = fmaf(sc, h23.x, a23.x);
    float aw = fmaf(sc, h23.y, a23.y);

    int beg = __ldg(&rowptr[v]);
    int end = __ldg(&rowptr[v + 1]);

    for (int j0 = beg; j0 < end; j0 += 32) {
        int j = j0 + lane;
        int2 ent = (j < end) ? __ldg(&csr[j]) : make_int2(0, 0);
        int kmax = min(32, end - j0);
        for (int k = 0; k < kmax; k++) {
            int s = __shfl_sync(0xFFFFFFFFu, ent.x, k);
            float c = __int_as_float(__shfl_sync(0xFFFFFFFFu, ent.y, k));
            uint2 sr = ((const uint2*)(h + (size_t)s * FD))[lane];
            float2 s01 = __half22float2(*(__half2*)&sr.x);
            float2 s23 = __half22float2(*(__half2*)&sr.y);
            ax = fmaf(c, s01.x, ax);
            ay = fmaf(c, s01.y, ay);
            az = fmaf(c, s23.x, az);
            aw = fmaf(c, s23.y, aw);
        }
    }
    __half2 o01 = __floats2half2_rn(ax, ay);
    __half2 o23 = __floats2half2_rn(az, aw);
    ((uint2*)(out + (size_t)v * FD))[lane] = make_uint2(*(unsigned*)&o01, *(unsigned*)&o23);
}

// ---------------- pair head (fp16 features) ----------------
__global__ void __launch_bounds__(256) k_pairs(const __half* __restrict__ h,
                                               const int* __restrict__ idx,
                                               const float* __restrict__ W3,
                                               const float* __restrict__ b3,
                                               float* __restrict__ out) {
    __shared__ float w[512];
    for (int t = threadIdx.x; t < 512; t += 256) w[t] = W3[t];
    __syncthreads();

    int p = (blockIdx.x * blockDim.x + threadIdx.x) >> 5;
    int lane = threadIdx.x & 31;
    if (p >= NP) return;

    int i0 = __ldg(&idx[2 * p]);
    int i1 = __ldg(&idx[2 * p + 1]);
    uint2 ar = ((const uint2*)(h + (size_t)i0 * FD))[lane];
    uint2 br = ((const uint2*)(h + (size_t)i1 * FD))[lane];
    float2 a01 = __half22float2(*(__half2*)&ar.x);
    float2 a23 = __half22float2(*(__half2*)&ar.y);
    float2 b01 = __half22float2(*(__half2*)&br.x);
    float2 b23 = __half22float2(*(__half2*)&br.y);
    float4 a = make_float4(fmaxf(a01.x, 0.f), fmaxf(a01.y, 0.f), fmaxf(a23.x, 0.f), fmaxf(a23.y, 0.f));
    float4 b = make_float4(fmaxf(b01.x, 0.f), fmaxf(b01.y, 0.f), fmaxf(b23.x, 0.f), fmaxf(b23.y, 0.f));

    float4 wa0 = *(const float4*)&w[lane * 4];
    float4 wb0 = *(const float4*)&w[128 + lane * 4];
    float4 wa1 = *(const float4*)&w[256 + lane * 4];
    float4 wb1 = *(const float4*)&w[384 + lane * 4];

    float s0 = a.x * wa0.x + a.y * wa0.y + a.z * wa0.z + a.w * wa0.w
             + b.x * wb0.x + b.y * wb0.y + b.z * wb0.z + b.w * wb0.w;
    float s1 = a.x * wa1.x + a.y * wa1.y + a.z * wa1.z + a.w * wa1.w
             + b.x * wb1.x + b.y * wb1.y + b.z * wb1.z + b.w * wb1.w;

#pragma unroll
    for (int o = 16; o > 0; o >>= 1) {
        s0 += __shfl_xor_sync(0xFFFFFFFFu, s0, o);
        s1 += __shfl_xor_sync(0xFFFFFFFFu, s1, o);
    }
    if (lane == 0) {
        float o0 = s0 + __ldg(&b3[0]);
        float o1 = s1 + __ldg(&b3[1]);
        float m = fmaxf(o0, o1);
        float lse = m + logf(expf(o0 - m) + expf(o1 - m));
        out[2 * p] = o0 - lse;
        out[2 * p + 1] = o1 - lse;
    }
}

// ---------------- launcher ----------------
extern "C" void kernel_launch(void* const* d_in, const int* in_sizes, int n_in,
                              void* d_out, int out_size) {
    const float* x     = (const float*)d_in[0];
    const int*   ei    = (const int*)d_in[1];
    const int*   index = (const int*)d_in[2];
    const float* W1    = (const float*)d_in[3];
    const float* b1    = (const float*)d_in[4];
    const float* W2    = (const float*)d_in[5];
    const float* b2    = (const float*)d_in[6];
    const float* W3    = (const float*)d_in[7];
    const float* b3    = (const float*)d_in[8];
    float* out = (float*)d_out;

    const int* src = ei;       // edge_index[0]
    const int* dst = ei + NE;  // edge_index[1]

    int *cnt, *rowptr, *cursor, *aux;
    float *dinv, *selfc;
    __half *a0, *ha16, *hb16, *W1h, *W2h;
    int2* csr;
    cudaGetSymbolAddress((void**)&cnt, g_cnt);
    cudaGetSymbolAddress((void**)&rowptr, g_rowptr);
    cudaGetSymbolAddress((void**)&cursor, g_cursor);
    cudaGetSymbolAddress((void**)&aux, g_aux);
    cudaGetSymbolAddress((void**)&dinv, g_dinv);
    cudaGetSymbolAddress((void**)&selfc, g_self);
    cudaGetSymbolAddress((void**)&csr, g_csr);
    cudaGetSymbolAddress((void**)&a0, g_a0);
    cudaGetSymbolAddress((void**)&ha16, g_ha16);
    cudaGetSymbolAddress((void**)&hb16, g_hb16);
    cudaGetSymbolAddress((void**)&W1h, g_W1h);
    cudaGetSymbolAddress((void**)&W2h, g_W2h);

    const int nodeG = (NN + 255) / 256;
    const int edgeG = (NE + 255) / 256;

    // prep + CSR build (once per launch)
    k_prep<<<nodeG, 256>>>(W1, W2, W1h, W2h, cnt);
    k_count<<<edgeG, 256>>>(dst, cnt);
    k_scan_block<<<SCAN_NB, SCAN_BS>>>(cnt, rowptr, aux, dinv, selfc);
    k_scan_aux<<<1, 128>>>(aux);
    k_scan_add<<<nodeG, 256>>>(rowptr, aux, cursor);
    k_fill<<<edgeG, 256>>>(src, dst, dinv, cursor, csr);

    const int gemm_grid = (NN + 31) / 32;
    const int warpNodeG = (int)(((size_t)NN * 32 + 255) / 256);
    const int pair_grid = (int)(((size_t)NP * 32 + 255) / 256);

    // h0 = x @ W1^T + b1  (fp16 anchor 0.1*h0 + fp16 state), tensor cores
    k_gemm_tc<false, false><<<gemm_grid, 128>>>(x, W1h, b1, a0, ha16, NN);

    // APPNP #1
    __half* bufs[2] = {hb16, ha16};
    __half* cur = ha16;
    for (int it = 0; it < KSTEPS; it++) {
        __half* nxt = bufs[it & 1];
        k_prop16<<<warpNodeG, 256>>>(rowptr, csr, cur, a0, selfc, nxt);
        cur = nxt;
    }

    // GEMM2: anchor/state from relu(cur) @ W2^T + b2 (state into ha16)
    k_gemm_tc<true, true><<<gemm_grid, 128>>>(cur, W2h, b2, a0, ha16, NN);

    // APPNP #2
    cur = ha16;
    for (int it = 0; it < KSTEPS; it++) {
        __half* nxt = bufs[it & 1];
        k_prop16<<<warpNodeG, 256>>>(rowptr, csr, cur, a0, selfc, nxt);
        cur = nxt;
    }

    // pair head on relu(cur)
    k_pairs<<<pair_grid, 256>>>(cur, index, W3, b3, out);
}

// round 11
// speedup vs baseline: 1.5561x; 1.0249x over previous
#include <cuda_runtime.h>
#include <cuda_fp16.h>
#include <cuda_bf16.h>
#include <cstdint>

#define NN 50000
#define NE 800000
#define NP 200000
#define FD 128
#define KSTEPS 10
#define SCAN_BS 512
#define SCAN_NB ((NN + SCAN_BS - 1) / SCAN_BS)   // 98

// ---- scratch (device globals; no allocation allowed) ----
__device__ int    g_cnt[NN];
__device__ int    g_rowptr[NN + 1];
__device__ int    g_cursor[NN];
__device__ int    g_aux[SCAN_NB];
__device__ float  g_dinv[NN];
__device__ float  g_self[NN];             // 0.9 * dinv^2 (self-loop coef)
__device__ int2   g_csr[NE];              // .x = src, .y = bitcast(0.9*dinv[s]*dinv[d])
__device__ __half g_a0[(size_t)NN * FD];  // fp16 teleport anchor = 0.1 * h0
__device__ __half g_ha16[(size_t)NN * FD];
__device__ __half g_hb16[(size_t)NN * FD];
__device__ __half g_W1h[FD * FD];
__device__ __half g_W2h[FD * FD];

static __device__ __forceinline__ uint32_t smem_u32(const void* p) {
    uint32_t a;
    asm("{ .reg .u64 t; cvta.to.shared.u64 t, %1; cvt.u32.u64 %0, t; }" : "=r"(a) : "l"(p));
    return a;
}

// ---------------- fused: weight fp32->fp16 + zero cnt ----------------
__global__ void k_prep(const float* __restrict__ W1, const float* __restrict__ W2,
                       __half* __restrict__ W1h, __half* __restrict__ W2h,
                       int* __restrict__ cnt) {
    int i = blockIdx.x * blockDim.x + threadIdx.x;
    if (i < NN) cnt[i] = 0;
    if (i < 4096) {
        float4 w = __ldg((const float4*)W1 + i);
        __half2 p0 = __floats2half2_rn(w.x, w.y);
        __half2 p1 = __floats2half2_rn(w.z, w.w);
        ((uint2*)W1h)[i] = make_uint2(*(unsigned*)&p0, *(unsigned*)&p1);
    } else if (i < 8192) {
        int j = i - 4096;
        float4 w = __ldg((const float4*)W2 + j);
        __half2 p0 = __floats2half2_rn(w.x, w.y);
        __half2 p1 = __floats2half2_rn(w.z, w.w);
        ((uint2*)W2h)[j] = make_uint2(*(unsigned*)&p0, *(unsigned*)&p1);
    }
}

__global__ void k_count(const int* __restrict__ dst, int* __restrict__ cnt) {
    int e = blockIdx.x * blockDim.x + threadIdx.x;
    if (e < NE) atomicAdd(&cnt[dst[e]], 1);
}

// scan_block fused with dinv/selfc computation (both read cnt)
__global__ void __launch_bounds__(SCAN_BS) k_scan_block(const int* __restrict__ cnt,
                                                        int* __restrict__ rowptr,
                                                        int* __restrict__ aux,
                                                        float* __restrict__ dinv,
                                                        float* __restrict__ selfc) {
    __shared__ int s[SCAN_BS];
    int i = blockIdx.x * SCAN_BS + threadIdx.x;
    int v = (i < NN) ? cnt[i] : 0;
    if (i < NN) {
        float d = rsqrtf((float)(v + 1));  // +1 self loop
        dinv[i] = d;
        selfc[i] = 0.9f * d * d;
    }
    s[threadIdx.x] = v;
    __syncthreads();
#pragma unroll
    for (int off = 1; off < SCAN_BS; off <<= 1) {
        int t = (threadIdx.x >= off) ? s[threadIdx.x - off] : 0;
        __syncthreads();
        s[threadIdx.x] += t;
        __syncthreads();
    }
    if (i < NN) rowptr[i] = s[threadIdx.x] - v;  // exclusive
    if (threadIdx.x == SCAN_BS - 1) aux[blockIdx.x] = s[threadIdx.x];
}

__global__ void __launch_bounds__(128) k_scan_aux(int* __restrict__ aux) {
    __shared__ int s[128];
    int v = (threadIdx.x < SCAN_NB) ? aux[threadIdx.x] : 0;
    s[threadIdx.x] = v;
    __syncthreads();
#pragma unroll
    for (int off = 1; off < 128; off <<= 1) {
        int t = (threadIdx.x >= off) ? s[threadIdx.x - off] : 0;
        __syncthreads();
        s[threadIdx.x] += t;
        __syncthreads();
    }
    if (threadIdx.x < SCAN_NB) aux[threadIdx.x] = s[threadIdx.x] - v;  // exclusive
}

__global__ void k_scan_add(int* __restrict__ rowptr, const int* __restrict__ aux,
                           int* __restrict__ cursor) {
    int i = blockIdx.x * blockDim.x + threadIdx.x;
    if (i < NN) {
        int r = rowptr[i] + aux[i / SCAN_BS];
        rowptr[i] = r;
        cursor[i] = r;
    }
    if (i == 0) rowptr[NN] = NE;
}

__global__ void k_fill(const int* __restrict__ src, const int* __restrict__ dst,
                       const float* __restrict__ dinv, int* __restrict__ cursor,
                       int2* __restrict__ csr) {
    int e = blockIdx.x * blockDim.x + threadIdx.x;
    if (e >= NE) return;
    int s = src[e], d = dst[e];
    int pos = atomicAdd(&cursor[d], 1);
    float w = 0.9f * dinv[s] * dinv[d];
    csr[pos] = make_int2(s, __float_as_int(w));
}

// ---------------- tensor-core GEMM: out = act(A)[rows,128] @ Wh[128,128]^T + b ----------------
template <bool RELU, bool IN_HALF>
__global__ void __launch_bounds__(128) k_gemm_tc(const void* __restrict__ Ain,
                                                 const __half* __restrict__ Wh,
                                                 const float* __restrict__ bias,
                                                 __half* __restrict__ anchor,
                                                 __half* __restrict__ out16, int rows) {
    __shared__ __half Ws[128][136];
    __shared__ __half As[32][136];

    int tid = threadIdx.x;
    int lane = tid & 31, warp = tid >> 5;
    int rowbase = blockIdx.x * 32;

    for (int t = tid; t < 2048; t += 128) {
        int j = t >> 4, g = t & 15;
        uint4 w = __ldg((const uint4*)(Wh + j * 128) + g);
        *(uint4*)&Ws[j][g * 8] = w;
    }
    for (int t = tid; t < 1024; t += 128) {
        int r = t >> 5, kq = t & 31;
        int row = rowbase + r;
        float4 v = make_float4(0.f, 0.f, 0.f, 0.f);
        if (row < rows) {
            if (IN_HALF) {
                uint2 u = __ldg((const uint2*)((const __half*)Ain + (size_t)row * 128 + kq * 4));
                float2 f01 = __half22float2(*(__half2*)&u.x);
                float2 f23 = __half22float2(*(__half2*)&u.y);
                v = make_float4(f01.x, f01.y, f23.x, f23.y);
            } else {
                v = __ldg((const float4*)((const float*)Ain + (size_t)row * 128 + kq * 4));
            }
        }
        if (RELU) {
            v.x = fmaxf(v.x, 0.f); v.y = fmaxf(v.y, 0.f);
            v.z = fmaxf(v.z, 0.f); v.w = fmaxf(v.w, 0.f);
        }
        __half2 p0 = __floats2half2_rn(v.x, v.y);
        __half2 p1 = __floats2half2_rn(v.z, v.w);
        *(uint2*)&As[r][kq * 4] = make_uint2(*(unsigned*)&p0, *(unsigned*)&p1);
    }
    __syncthreads();

    int r0 = (warp >> 1) * 16;
    int jbase = (warp & 1) * 64;

    uint32_t as_base = smem_u32(&As[0][0]);
    uint32_t ws_base = smem_u32(&Ws[0][0]);
    uint32_t a_addr0 = as_base + (uint32_t)(((r0 + (lane & 15)) * 136 + ((lane >> 4) * 8)) * 2);
    uint32_t b_addr0 = ws_base + (uint32_t)((((jbase + (lane & 7)) * 136) + (((lane >> 3) & 1) * 8)) * 2);

    float d[8][4];
#pragma unroll
    for (int t = 0; t < 8; t++)
        d[t][0] = d[t][1] = d[t][2] = d[t][3] = 0.f;

#pragma unroll
    for (int k0 = 0; k0 < 128; k0 += 16) {
        uint32_t a0, a1, a2, a3;
        asm volatile("ldmatrix.sync.aligned.m8n8.x4.shared.b16 {%0,%1,%2,%3}, [%4];"
                     : "=r"(a0), "=r"(a1), "=r"(a2), "=r"(a3)
                     : "r"(a_addr0 + (uint32_t)(k0 * 2)));
#pragma unroll
        for (int t = 0; t < 8; t++) {
            uint32_t b0, b1;
            asm volatile("ldmatrix.sync.aligned.m8n8.x2.shared.b16 {%0,%1}, [%2];"
                         : "=r"(b0), "=r"(b1)
                         : "r"(b_addr0 + (uint32_t)((t * 8 * 136 + k0) * 2)));
            asm volatile("mma.sync.aligned.m16n8k16.row.col.f32.f16.f16.f32 "
                         "{%0,%1,%2,%3}, {%4,%5,%6,%7}, {%8,%9}, {%0,%1,%2,%3};"
                         : "+f"(d[t][0]), "+f"(d[t][1]), "+f"(d[t][2]), "+f"(d[t][3])
                         : "r"(a0), "r"(a1), "r"(a2), "r"(a3), "r"(b0), "r"(b1));
        }
    }

    int row0 = rowbase + r0 + (lane >> 2);
    int row1 = row0 + 8;
#pragma unroll
    for (int t = 0; t < 8; t++) {
        int col = jbase + t * 8 + 2 * (lane & 3);
        float bx = __ldg(&bias[col]);
        float by = __ldg(&bias[col + 1]);
        if (row0 < rows) {
            float v0 = d[t][0] + bx, v1 = d[t][1] + by;
            __half2 hs = __floats2half2_rn(v0, v1);
            __half2 hanc = __floats2half2_rn(0.1f * v0, 0.1f * v1);
            *(unsigned*)(out16 + (size_t)row0 * 128 + col) = *(unsigned*)&hs;
            *(unsigned*)(anchor + (size_t)row0 * 128 + col) = *(unsigned*)&hanc;
        }
        if (row1 < rows) {
            float v2 = d[t][2] + bx, v3 = d[t][3] + by;
            __half2 hs = __floats2half2_rn(v2, v3);
            __half2 hanc = __floats2half2_rn(0.1f * v2, 0.1f * v3);
            *(unsigned*)(out16 + (size_t)row1 * 128 + col) = *(unsigned*)&hs;
            *(unsigned*)(anchor + (size_t)row1 * 128 + col) = *(unsigned*)&hanc;
        }
    }
}

// ---------------- fused APPNP step (fp16 state + anchor, 2-deep pipelined gather) ----------------
// out[v] = a0[v] + selfc[v]*h[v] + sum_{e: dst=v} w[e]*h[src[e]]
// Single change vs R8-proven form: prefetch edge k+1's source row before consuming
// edge k's (MLP 1 -> 2). Adds only r_nxt/c_nxt live registers.
__global__ void __launch_bounds__(256) k_prop16(const int* __restrict__ rowptr,
                                                const int2* __restrict__ csr,
                                                const __half* __restrict__ h,
                                                const __half* __restrict__ a0,
                                                const float* __restrict__ selfc,
                                                __half* __restrict__ out) {
    int v = (blockIdx.x * blockDim.x + threadIdx.x) >> 5;
    int lane = threadIdx.x & 31;
    if (v >= NN) return;

    float sc = __ldg(&selfc[v]);
    uint2 hr = ((const uint2*)(h + (size_t)v * FD))[lane];
    float2 h01 = __half22float2(*(__half2*)&hr.x);
    float2 h23 = __half22float2(*(__half2*)&hr.y);
    uint2 ar = ((const uint2*)(a0 + (size_t)v * FD))[lane];
    float2 a01 = __half22float2(*(__half2*)&ar.x);
    float2 a23 = __half22float2(*(__half2*)&ar.y);
    float ax = fmaf(sc, h01.x, a01.x);
    float ay = fmaf(sc, h01.y, a01.y);
    float az = fmaf(sc, h23.x, a23.x);
    float aw = fmaf(sc, h23.y, a23.y);

    int beg = __ldg(&rowptr[v]);
    int end = __ldg(&rowptr[v + 1]);

    for (int j0 = beg; j0 < end; j0 += 32) {
        int j = j0 + lane;
        int2 ent = (j < end) ? __ldg(&csr[j]) : make_int2(0, 0);
        int kmax = min(32, end - j0);

        // prime: issue gather for k=0
        int s_cur = __shfl_sync(0xFFFFFFFFu, ent.x, 0);
        float c_cur = __int_as_float(__shfl_sync(0xFFFFFFFFu, ent.y, 0));
        uint2 r_cur = __ldg((const uint2*)(h + (size_t)s_cur * FD) + lane);

        for (int k = 1; k < kmax; k++) {
            // issue gather k before consuming gather k-1
            int s_nxt = __shfl_sync(0xFFFFFFFFu, ent.x, k);
            float c_nxt = __int_as_float(__shfl_sync(0xFFFFFFFFu, ent.y, k));
            uint2 r_nxt = __ldg((const uint2*)(h + (size_t)s_nxt * FD) + lane);

            float2 s01 = __half22float2(*(__half2*)&r_cur.x);
            float2 s23 = __half22float2(*(__half2*)&r_cur.y);
            ax = fmaf(c_cur, s01.x, ax);
            ay = fmaf(c_cur, s01.y, ay);
            az = fmaf(c_cur, s23.x, az);
            aw = fmaf(c_cur, s23.y, aw);

            r_cur = r_nxt;
            c_cur = c_nxt;
        }
        // drain last
        {
            float2 s01 = __half22float2(*(__half2*)&r_cur.x);
            float2 s23 = __half22float2(*(__half2*)&r_cur.y);
            ax = fmaf(c_cur, s01.x, ax);
            ay = fmaf(c_cur, s01.y, ay);
            az = fmaf(c_cur, s23.x, az);
            aw = fmaf(c_cur, s23.y, aw);
        }
    }
    __half2 o01 = __floats2half2_rn(ax, ay);
    __half2 o23 = __floats2half2_rn(az, aw);
    ((uint2*)(out + (size_t)v * FD))[lane] = make_uint2(*(unsigned*)&o01, *(unsigned*)&o23);
}

// ---------------- pair head (fp16 features) ----------------
__global__ void __launch_bounds__(256) k_pairs(const __half* __restrict__ h,
                                               const int* __restrict__ idx,
                                               const float* __restrict__ W3,
                                               const float* __restrict__ b3,
                                               float* __restrict__ out) {
    __shared__ float w[512];
    for (int t = threadIdx.x; t < 512; t += 256) w[t] = W3[t];
    __syncthreads();

    int p = (blockIdx.x * blockDim.x + threadIdx.x) >> 5;
    int lane = threadIdx.x & 31;
    if (p >= NP) return;

    int i0 = __ldg(&idx[2 * p]);
    int i1 = __ldg(&idx[2 * p + 1]);
    uint2 ar = ((const uint2*)(h + (size_t)i0 * FD))[lane];
    uint2 br = ((const uint2*)(h + (size_t)i1 * FD))[lane];
    float2 a01 = __half22float2(*(__half2*)&ar.x);
    float2 a23 = __half22float2(*(__half2*)&ar.y);
    float2 b01 = __half22float2(*(__half2*)&br.x);
    float2 b23 = __half22float2(*(__half2*)&br.y);
    float4 a = make_float4(fmaxf(a01.x, 0.f), fmaxf(a01.y, 0.f), fmaxf(a23.x, 0.f), fmaxf(a23.y, 0.f));
    float4 b = make_float4(fmaxf(b01.x, 0.f), fmaxf(b01.y, 0.f), fmaxf(b23.x, 0.f), fmaxf(b23.y, 0.f));

    float4 wa0 = *(const float4*)&w[lane * 4];
    float4 wb0 = *(const float4*)&w[128 + lane * 4];
    float4 wa1 = *(const float4*)&w[256 + lane * 4];
    float4 wb1 = *(const float4*)&w[384 + lane * 4];

    float s0 = a.x * wa0.x + a.y * wa0.y + a.z * wa0.z + a.w * wa0.w
             + b.x * wb0.x + b.y * wb0.y + b.z * wb0.z + b.w * wb0.w;
    float s1 = a.x * wa1.x + a.y * wa1.y + a.z * wa1.z + a.w * wa1.w
             + b.x * wb1.x + b.y * wb1.y + b.z * wb1.z + b.w * wb1.w;

#pragma unroll
    for (int o = 16; o > 0; o >>= 1) {
        s0 += __shfl_xor_sync(0xFFFFFFFFu, s0, o);
        s1 += __shfl_xor_sync(0xFFFFFFFFu, s1, o);
    }
    if (lane == 0) {
        float o0 = s0 + __ldg(&b3[0]);
        float o1 = s1 + __ldg(&b3[1]);
        float m = fmaxf(o0, o1);
        float lse = m + logf(expf(o0 - m) + expf(o1 - m));
        out[2 * p] = o0 - lse;
        out[2 * p + 1] = o1 - lse;
    }
}

// ---------------- launcher ----------------
extern "C" void kernel_launch(void* const* d_in, const int* in_sizes, int n_in,
                              void* d_out, int out_size) {
    const float* x     = (const float*)d_in[0];
    const int*   ei    = (const int*)d_in[1];
    const int*   index = (const int*)d_in[2];
    const float* W1    = (const float*)d_in[3];
    const float* b1    = (const float*)d_in[4];
    const float* W2    = (const float*)d_in[5];
    const float* b2    = (const float*)d_in[6];
    const float* W3    = (const float*)d_in[7];
    const float* b3    = (const float*)d_in[8];
    float* out = (float*)d_out;

    const int* src = ei;       // edge_index[0]
    const int* dst = ei + NE;  // edge_index[1]

    int *cnt, *rowptr, *cursor, *aux;
    float *dinv, *selfc;
    __half *a0, *ha16, *hb16, *W1h, *W2h;
    int2* csr;
    cudaGetSymbolAddress((void**)&cnt, g_cnt);
    cudaGetSymbolAddress((void**)&rowptr, g_rowptr);
    cudaGetSymbolAddress((void**)&cursor, g_cursor);
    cudaGetSymbolAddress((void**)&aux, g_aux);
    cudaGetSymbolAddress((void**)&dinv, g_dinv);
    cudaGetSymbolAddress((void**)&selfc, g_self);
    cudaGetSymbolAddress((void**)&csr, g_csr);
    cudaGetSymbolAddress((void**)&a0, g_a0);
    cudaGetSymbolAddress((void**)&ha16, g_ha16);
    cudaGetSymbolAddress((void**)&hb16, g_hb16);
    cudaGetSymbolAddress((void**)&W1h, g_W1h);
    cudaGetSymbolAddress((void**)&W2h, g_W2h);

    const int nodeG = (NN + 255) / 256;
    const int edgeG = (NE + 255) / 256;

    // prep + CSR build (once per launch)
    k_prep<<<nodeG, 256>>>(W1, W2, W1h, W2h, cnt);
    k_count<<<edgeG, 256>>>(dst, cnt);
    k_scan_block<<<SCAN_NB, SCAN_BS>>>(cnt, rowptr, aux, dinv, selfc);
    k_scan_aux<<<1, 128>>>(aux);
    k_scan_add<<<nodeG, 256>>>(rowptr, aux, cursor);
    k_fill<<<edgeG, 256>>>(src, dst, dinv, cursor, csr);

    const int gemm_grid = (NN + 31) / 32;
    const int warpNodeG = (int)(((size_t)NN * 32 + 255) / 256);
    const int pair_grid = (int)(((size_t)NP * 32 + 255) / 256);

    // h0 = x @ W1^T + b1  (fp16 anchor 0.1*h0 + fp16 state), tensor cores
    k_gemm_tc<false, false><<<gemm_grid, 128>>>(x, W1h, b1, a0, ha16, NN);

    // APPNP #1
    __half* bufs[2] = {hb16, ha16};
    __half* cur = ha16;
    for (int it = 0; it < KSTEPS; it++) {
        __half* nxt = bufs[it & 1];
        k_prop16<<<warpNodeG, 256>>>(rowptr, csr, cur, a0, selfc, nxt);
        cur = nxt;
    }

    // GEMM2: anchor/state from relu(cur) @ W2^T + b2 (state into ha16)
    k_gemm_tc<true, true><<<gemm_grid, 128>>>(cur, W2h, b2, a0, ha16, NN);

    // APPNP #2
    cur = ha16;
    for (int it = 0; it < KSTEPS; it++) {
        __half* nxt = bufs[it & 1];
        k_prop16<<<warpNodeG, 256>>>(rowptr, csr, cur, a0, selfc, nxt);
        cur = nxt;
    }

    // pair head on relu(cur)
    k_pairs<<<pair_grid, 256>>>(cur, index, W3, b3, out);
}